// round 14
// baseline (speedup 1.0000x reference)
#include <cuda_runtime.h>
#include <cuda_fp16.h>
#include <math_constants.h>
#include <cstdint>

// Problem constants (fixed shapes)
#define BB 8
#define SS 2048
#define NN 8192
#define FF 256
#define CC 128
#define DIN 384
#define DH 512
#define ROWS (BB * NN)          // 65536
#define NBM (ROWS / 128)        // 512 row-tiles
#define EPSW 1.1920928955078125e-7f
#define BN_EPS 1e-5f

// -------- scratch (device globals; no allocation allowed) --------
__device__ __half g_x0h[(size_t)ROWS * DIN];    // fp16 concat(point_features, interp)
__device__ __half g_y1h[(size_t)ROWS * DH];     // fp16 GEMM1 out, then BN+GELU in-place
__device__ __half g_w1t[(size_t)DH * DIN];      // W1 transposed [n][k] fp16
__device__ __half g_w2t[(size_t)DH * DH];       // W2 transposed [n][k] fp16
__device__ float  g_part[2 * DH * NBM];         // [stat][col][bm] deterministic partials
__device__ float  g_scale[DH];
__device__ float  g_shift[DH];

// ======================= PTX helpers (portable sm_80+ subset) =======================
__device__ __forceinline__ uint32_t smem_u32(const void* p) {
    uint32_t a;
    asm("{ .reg .u64 t; cvta.to.shared.u64 t, %1; cvt.u32.u64 %0, t; }" : "=r"(a) : "l"(p));
    return a;
}
__device__ __forceinline__ void cp_async16(uint32_t dst, const void* src) {
    asm volatile("cp.async.cg.shared.global [%0], [%1], 16;" :: "r"(dst), "l"(src));
}
__device__ __forceinline__ void ldsm_x4(uint32_t* r, uint32_t addr) {
    asm volatile("ldmatrix.sync.aligned.m8n8.x4.shared.b16 {%0,%1,%2,%3}, [%4];"
                 : "=r"(r[0]), "=r"(r[1]), "=r"(r[2]), "=r"(r[3]) : "r"(addr));
}
__device__ __forceinline__ void mma16816(float* d, const uint32_t* a, const uint32_t* b) {
    asm volatile("mma.sync.aligned.m16n8k16.row.col.f32.f16.f16.f32 "
                 "{%0,%1,%2,%3}, {%4,%5,%6,%7}, {%8,%9}, {%0,%1,%2,%3};"
                 : "+f"(d[0]), "+f"(d[1]), "+f"(d[2]), "+f"(d[3])
                 : "r"(a[0]), "r"(a[1]), "r"(a[2]), "r"(a[3]), "r"(b[0]), "r"(b[1]));
}

// ======================= 1. 3-NN + interpolation (writes fp16) =======================
__global__ void interp_kernel(const float* __restrict__ sxyz,
                              const float* __restrict__ spf,
                              const float* __restrict__ xyz,
                              const float* __restrict__ pf) {
    __shared__ float sx[SS], sy[SS], sz[SS], sn[SS];
    __shared__ int   sidx[128][3];
    __shared__ float sw[128][3];

    const int b     = blockIdx.x >> 6;
    const int chunk = blockIdx.x & 63;
    const int t     = threadIdx.x;

    const float* sb = sxyz + (size_t)b * SS * 3;
    for (int s = t; s < SS; s += 128) {
        float x = sb[s * 3 + 0], y = sb[s * 3 + 1], z = sb[s * 3 + 2];
        sx[s] = x; sy[s] = y; sz[s] = z;
        sn[s] = x * x + y * y + z * z;
    }
    __syncthreads();

    const int p = chunk * 128 + t;
    const size_t prow = (size_t)b * NN + p;
    const float px = xyz[prow * 3 + 0];
    const float py = xyz[prow * 3 + 1];
    const float pz = xyz[prow * 3 + 2];
    const float n1 = px * px + py * py + pz * pz;

    float d0 = CUDART_INF_F, d1 = CUDART_INF_F, d2 = CUDART_INF_F;
    int   i0 = 0, i1 = 0, i2 = 0;
#pragma unroll 4
    for (int s = 0; s < SS; s++) {
        float dot = fmaf(px, sx[s], fmaf(py, sy[s], pz * sz[s]));
        float d = __fadd_rn(__fadd_rn(__fmul_rn(-2.0f, dot), n1), sn[s]);
        if (d < d0)      { d2 = d1; i2 = i1; d1 = d0; i1 = i0; d0 = d; i0 = s; }
        else if (d < d1) { d2 = d1; i2 = i1; d1 = d;  i1 = s; }
        else if (d < d2) { d2 = d;  i2 = s; }
    }
    float w0 = 1.0f / (fmaxf(d0, 0.0f) + EPSW);
    float w1 = 1.0f / (fmaxf(d1, 0.0f) + EPSW);
    float w2 = 1.0f / (fmaxf(d2, 0.0f) + EPSW);
    float wsum = (w0 + w1) + w2;
    sidx[t][0] = i0; sidx[t][1] = i1; sidx[t][2] = i2;
    sw[t][0] = w0 / wsum; sw[t][1] = w1 / wsum; sw[t][2] = w2 / wsum;
    __syncthreads();

    const float* fb = spf + (size_t)b * SS * FF;
    const size_t rowbase = (size_t)b * NN + (size_t)chunk * 128;

    // gather: 2 points per iteration, float4 loads, uint2 (4xfp16) stores
    const int half_id = t >> 6;     // 0/1 -> which point of the pair
    const int tt = t & 63;          // float4 chunk within the 256-wide feature row
    for (int pl2 = 0; pl2 < 64; pl2++) {
        const int pl = pl2 * 2 + half_id;
        const int   j0 = sidx[pl][0], j1 = sidx[pl][1], j2 = sidx[pl][2];
        const float a0 = sw[pl][0],   a1 = sw[pl][1],   a2 = sw[pl][2];
        const float4* r0 = (const float4*)(fb + (size_t)j0 * FF);
        const float4* r1 = (const float4*)(fb + (size_t)j1 * FF);
        const float4* r2 = (const float4*)(fb + (size_t)j2 * FF);
        float4 v0 = r0[tt], v1 = r1[tt], v2 = r2[tt];
        float ax = (a0 * v0.x + a1 * v1.x) + a2 * v2.x;
        float ay = (a0 * v0.y + a1 * v1.y) + a2 * v2.y;
        float az = (a0 * v0.z + a1 * v1.z) + a2 * v2.z;
        float aw = (a0 * v0.w + a1 * v1.w) + a2 * v2.w;
        __half2 p0 = __floats2half2_rn(ax, ay);
        __half2 p1 = __floats2half2_rn(az, aw);
        uint2 u;
        u.x = *reinterpret_cast<uint32_t*>(&p0);
        u.y = *reinterpret_cast<uint32_t*>(&p1);
        *reinterpret_cast<uint2*>(g_x0h + (rowbase + pl) * DIN + CC + tt * 4) = u;
    }
    // copy point_features (128 cols) via float4 -> 4xfp16
    for (int idx = t; idx < 128 * CC / 4; idx += 128) {
        int pl = idx >> 5;          // 32 float4 per row
        int f4 = idx & 31;
        float4 v = ((const float4*)(pf + (rowbase + pl) * CC))[f4];
        __half2 p0 = __floats2half2_rn(v.x, v.y);
        __half2 p1 = __floats2half2_rn(v.z, v.w);
        uint2 u;
        u.x = *reinterpret_cast<uint32_t*>(&p0);
        u.y = *reinterpret_cast<uint32_t*>(&p1);
        *reinterpret_cast<uint2*>(g_x0h + (rowbase + pl) * DIN + f4 * 4) = u;
    }
}

// ======================= 2. weight prep: transpose to [n][k] fp16 =======================
__global__ void wprep_kernel(const float* __restrict__ W, __half* __restrict__ Wt, int K) {
    int i = blockIdx.x * blockDim.x + threadIdx.x;
    if (i >= K * DH) return;
    int k = i / DH, n = i % DH;
    Wt[(size_t)n * K + k] = __float2half(W[i]);
}

// ======================= 3. fp16 HGEMM (mma.sync m16n8k16) + fused BN stats =======================
// C tile 128x128, 4 warps (2x2), warp tile 64x64, BK=64, 3-stage cp.async pipeline.
// 8 ldmatrix.x4 per 32 MMAs (vs 6 per 16 previously) -> 33% less smem read traffic.
// Epilogue: stores C (fp16 or fp32) AND deterministic per-(col,bm) sum/sumsq partials.
#define HG_STAGE_BYTES 32768                 // A 16KB + B 16KB per stage
#define HG_SMEM (3 * HG_STAGE_BYTES)         // 96KB

template <int HALF_OUT>
__global__ __launch_bounds__(128, 2) void hgemm_kernel(
    const __half* __restrict__ A, const __half* __restrict__ Bt,
    void* __restrict__ Cv, int K) {
    extern __shared__ char smem[];
    const uint32_t sbase = smem_u32(smem);
    const int tid = threadIdx.x, wid = tid >> 5, lane = tid & 31;
    const int bn = blockIdx.x, bm = blockIdx.y;
    const int wm = wid >> 1, wn = wid & 1;     // 2 x 2 warp grid, tile 64x64

    const int lr = tid >> 3, lj = tid & 7;     // 16 rows x 8 chunks per pass, 8 passes
    const __half* ag = A + (size_t)(bm * 128) * K + lj * 8;
    const __half* bg = Bt + (size_t)(bn * 128) * K + lj * 8;

    float acc[4][8][4];
#pragma unroll
    for (int i = 0; i < 4; i++)
#pragma unroll
        for (int j = 0; j < 8; j++)
#pragma unroll
            for (int q = 0; q < 4; q++) acc[i][j][q] = 0.0f;

    auto load = [&](int c, int st) {
        uint32_t dA = sbase + st * HG_STAGE_BYTES;
        uint32_t dB = dA + 16384;
        const __half* a = ag + c * 64;
        const __half* b = bg + c * 64;
#pragma unroll
        for (int i = 0; i < 8; i++) {
            int r = lr + 16 * i;
            uint32_t so = (uint32_t)(r * 128 + lj * 16) ^ (uint32_t)((r & 7) << 4);
            cp_async16(dA + so, a + (size_t)r * K);
            cp_async16(dB + so, b + (size_t)r * K);
        }
        asm volatile("cp.async.commit_group;" ::: "memory");
    };

    const int CHN = K >> 6;
    load(0, 0);
    load(1, 1);
    for (int c = 0; c < CHN; c++) {
        const int st = c - (c / 3) * 3;   // c % 3
        if (c + 2 < CHN) {
            load(c + 2, (c + 2) - ((c + 2) / 3) * 3);
            asm volatile("cp.async.wait_group 2;" ::: "memory");
        } else if (c + 1 < CHN) {
            asm volatile("cp.async.wait_group 1;" ::: "memory");
        } else {
            asm volatile("cp.async.wait_group 0;" ::: "memory");
        }
        __syncthreads();

        const uint32_t sA = sbase + st * HG_STAGE_BYTES;
        const uint32_t sB = sA + 16384;
#pragma unroll
        for (int s = 0; s < 4; s++) {
            uint32_t af[4][4];
            uint32_t bf[8][2];
#pragma unroll
            for (int i = 0; i < 4; i++) {
                int row = wm * 64 + i * 16 + (lane & 15);
                uint32_t off = (uint32_t)(row * 128 + s * 32 + (lane >> 4) * 16)
                             ^ (uint32_t)((row & 7) << 4);
                ldsm_x4(af[i], sA + off);
            }
#pragma unroll
            for (int u = 0; u < 4; u++) {
                int n  = wn * 64 + u * 16 + ((lane >> 4) * 8) + (lane & 7);
                int kh = (lane >> 3) & 1;
                uint32_t off = (uint32_t)(n * 128 + s * 32 + kh * 16)
                             ^ (uint32_t)((n & 7) << 4);
                uint32_t r4[4];
                ldsm_x4(r4, sB + off);
                bf[2 * u][0] = r4[0]; bf[2 * u][1] = r4[1];
                bf[2 * u + 1][0] = r4[2]; bf[2 * u + 1][1] = r4[3];
            }
#pragma unroll
            for (int i = 0; i < 4; i++)
#pragma unroll
                for (int j = 0; j < 8; j++)
                    mma16816(acc[i][j], af[i], bf[j]);
        }
        __syncthreads();
    }

    // ---- epilogue: store C ----
    const int r = lane >> 2, cc = (lane & 3) * 2;
    if (HALF_OUT) {
        __half* Cp = (__half*)Cv + (size_t)(bm * 128 + wm * 64) * DH + bn * 128 + wn * 64;
#pragma unroll
        for (int i = 0; i < 4; i++) {
#pragma unroll
            for (int j = 0; j < 8; j++) {
                __half2 v0 = __floats2half2_rn(acc[i][j][0], acc[i][j][1]);
                __half2 v1 = __floats2half2_rn(acc[i][j][2], acc[i][j][3]);
                *(__half2*)(Cp + (size_t)(i * 16 + r) * DH + j * 8 + cc) = v0;
                *(__half2*)(Cp + (size_t)(i * 16 + r + 8) * DH + j * 8 + cc) = v1;
            }
        }
    } else {
        float* Cp = (float*)Cv + (size_t)(bm * 128 + wm * 64) * DH + bn * 128 + wn * 64;
#pragma unroll
        for (int i = 0; i < 4; i++) {
#pragma unroll
            for (int j = 0; j < 8; j++) {
                float2 v0 = make_float2(acc[i][j][0], acc[i][j][1]);
                float2 v1 = make_float2(acc[i][j][2], acc[i][j][3]);
                *(float2*)(Cp + (size_t)(i * 16 + r) * DH + j * 8 + cc) = v0;
                *(float2*)(Cp + (size_t)(i * 16 + r + 8) * DH + j * 8 + cc) = v1;
            }
        }
    }

    // ---- epilogue: deterministic per-(col, bm) BN partials from fp32 accumulators ----
    // per-thread: 16 column slots (j in 0..7, qp in 0..1); sum over i and row halves
    float sS[16], sQ[16];
#pragma unroll
    for (int j = 0; j < 8; j++) {
#pragma unroll
        for (int qp = 0; qp < 2; qp++) {
            float s = 0.f, q = 0.f;
#pragma unroll
            for (int i = 0; i < 4; i++) {
                float a = acc[i][j][qp];
                float b = acc[i][j][2 + qp];
                s += a + b;
                q += a * a + b * b;
            }
            sS[j * 2 + qp] = s;
            sQ[j * 2 + qp] = q;
        }
    }
    // reduce over the 8 row-lanes (lanes sharing lane&3): xor tree, fixed order
#pragma unroll
    for (int off = 4; off <= 16; off <<= 1) {
#pragma unroll
        for (int sl = 0; sl < 16; sl++) {
            sS[sl] += __shfl_xor_sync(0xFFFFFFFFu, sS[sl], off);
            sQ[sl] += __shfl_xor_sync(0xFFFFFFFFu, sQ[sl], off);
        }
    }
    // stage per-warp 64-col results in smem: [wm][stat][128 cols]
    float* sbuf = (float*)smem;   // safe: all cp.async done, barrier below orders reuse
    __syncthreads();
    if (lane < 4) {
#pragma unroll
        for (int j = 0; j < 8; j++) {
#pragma unroll
            for (int qp = 0; qp < 2; qp++) {
                int col = wn * 64 + j * 8 + lane * 2 + qp;
                sbuf[(wm * 2 + 0) * 128 + col] = sS[j * 2 + qp];
                sbuf[(wm * 2 + 1) * 128 + col] = sQ[j * 2 + qp];
            }
        }
    }
    __syncthreads();
    if (tid < 128) {
        float S = sbuf[0 * 128 + tid] + sbuf[2 * 128 + tid];
        float Q = sbuf[1 * 128 + tid] + sbuf[3 * 128 + tid];
        int colg = bn * 128 + tid;
        g_part[0 * DH * NBM + (size_t)colg * NBM + bm] = S;
        g_part[1 * DH * NBM + (size_t)colg * NBM + bm] = Q;
    }
}

// ======================= 4. finalize BN: reduce 512 partials per column =======================
__global__ void finalize_bn_kernel(const float* __restrict__ gamma,
                                   const float* __restrict__ beta) {
    const int c = blockIdx.x;
    const int t = threadIdx.x;   // 256
    float s = g_part[(size_t)c * NBM + t] + g_part[(size_t)c * NBM + t + 256];
    float q = g_part[DH * NBM + (size_t)c * NBM + t] +
              g_part[DH * NBM + (size_t)c * NBM + t + 256];
#pragma unroll
    for (int o = 16; o > 0; o >>= 1) {
        s += __shfl_down_sync(0xFFFFFFFFu, s, o);
        q += __shfl_down_sync(0xFFFFFFFFu, q, o);
    }
    __shared__ float ss[8], qq[8];
    if ((t & 31) == 0) { ss[t >> 5] = s; qq[t >> 5] = q; }
    __syncthreads();
    if (t == 0) {
        float S = 0.f, Q = 0.f;
#pragma unroll
        for (int i = 0; i < 8; i++) { S += ss[i]; Q += qq[i]; }
        const float inv = 1.0f / (float)ROWS;
        float mean = S * inv;
        float var  = Q * inv - mean * mean;
        float sc = gamma[c] * rsqrtf(var + BN_EPS);
        g_scale[c] = sc;
        g_shift[c] = beta[c] - mean * sc;
    }
}

// ======================= 5. fused BN + exact GELU =======================
__device__ __forceinline__ float gelu_exact(float x) {
    return 0.5f * x * (1.0f + erff(x * 0.70710678118654752f));
}

// layer-1: in-place on fp16 y1h (4 halves per thread)
__global__ void bn_gelu_h_kernel(__half* __restrict__ H) {
    const int i = blockIdx.x * blockDim.x + threadIdx.x;   // 4-half chunk index
    uint2 u = ((const uint2*)H)[i];
    __half2 p0 = *reinterpret_cast<__half2*>(&u.x);
    __half2 p1 = *reinterpret_cast<__half2*>(&u.y);
    const int col = (i * 4) & (DH - 1);
    float t0 = gelu_exact(__half2float(p0.x) * g_scale[col + 0] + g_shift[col + 0]);
    float t1 = gelu_exact(__half2float(p0.y) * g_scale[col + 1] + g_shift[col + 1]);
    float t2 = gelu_exact(__half2float(p1.x) * g_scale[col + 2] + g_shift[col + 2]);
    float t3 = gelu_exact(__half2float(p1.y) * g_scale[col + 3] + g_shift[col + 3]);
    __half2 q0 = __floats2half2_rn(t0, t1);
    __half2 q1 = __floats2half2_rn(t2, t3);
    u.x = *reinterpret_cast<uint32_t*>(&q0);
    u.y = *reinterpret_cast<uint32_t*>(&q1);
    ((uint2*)H)[i] = u;
}

// final layer: in-place fp32
__global__ void bn_gelu_kernel(float* __restrict__ Y) {
    const int i = blockIdx.x * blockDim.x + threadIdx.x;
    float4 v = ((float4*)Y)[i];
    const int col = (i * 4) & (DH - 1);
    v.x = gelu_exact(v.x * g_scale[col + 0] + g_shift[col + 0]);
    v.y = gelu_exact(v.y * g_scale[col + 1] + g_shift[col + 1]);
    v.z = gelu_exact(v.z * g_scale[col + 2] + g_shift[col + 2]);
    v.w = gelu_exact(v.w * g_scale[col + 3] + g_shift[col + 3]);
    ((float4*)Y)[i] = v;
}

// ======================= host launch =======================
extern "C" void kernel_launch(void* const* d_in, const int* in_sizes, int n_in,
                              void* d_out, int out_size) {
    const float* sxyz = (const float*)d_in[0];
    const float* spf  = (const float*)d_in[1];
    const float* xyz  = (const float*)d_in[2];
    const float* pf   = (const float*)d_in[3];
    const float* W1   = (const float*)d_in[4];
    const float* g1   = (const float*)d_in[5];
    const float* b1   = (const float*)d_in[6];
    const float* W2   = (const float*)d_in[7];
    const float* g2   = (const float*)d_in[8];
    const float* b2   = (const float*)d_in[9];
    float* out = (float*)d_out;

    void *p_x0h, *p_y1h, *p_w1t, *p_w2t;
    cudaGetSymbolAddress(&p_x0h, g_x0h);
    cudaGetSymbolAddress(&p_y1h, g_y1h);
    cudaGetSymbolAddress(&p_w1t, g_w1t);
    cudaGetSymbolAddress(&p_w2t, g_w2t);

    cudaFuncSetAttribute(hgemm_kernel<1>, cudaFuncAttributeMaxDynamicSharedMemorySize, HG_SMEM);
    cudaFuncSetAttribute(hgemm_kernel<0>, cudaFuncAttributeMaxDynamicSharedMemorySize, HG_SMEM);

    // 1. 3-NN interpolation + concat -> x0 fp16 [65536, 384]
    interp_kernel<<<BB * 64, 128>>>(sxyz, spf, xyz, pf);

    // 2. weight transpose to fp16 (tiny)
    wprep_kernel<<<(DIN * DH + 255) / 256, 256>>>(W1, (__half*)p_w1t, DIN);
    wprep_kernel<<<(DH * DH + 255) / 256, 256>>>(W2, (__half*)p_w2t, DH);

    // 3. y1h = x0 @ W1 (fp16 out) + fused BN partials
    {
        dim3 grid(DH / 128, ROWS / 128);
        hgemm_kernel<1><<<grid, 128, HG_SMEM>>>((const __half*)p_x0h, (const __half*)p_w1t,
                                                p_y1h, DIN);
    }

    // 4. finalize BN-1, then fused BN+GELU in-place on y1h (fp16)
    finalize_bn_kernel<<<DH, 256>>>(g1, b1);
    bn_gelu_h_kernel<<<(ROWS * DH / 4) / 256, 256>>>((__half*)p_y1h);

    // 5. out = y1h @ W2 (fp32 out) + fused BN partials
    {
        dim3 grid(DH / 128, ROWS / 128);
        hgemm_kernel<0><<<grid, 128, HG_SMEM>>>((const __half*)p_y1h, (const __half*)p_w2t,
                                                out, DH);
    }

    // 6. finalize BN-2 + fused BN+GELU in-place on out (fp32)
    finalize_bn_kernel<<<DH, 256>>>(g2, b2);
    bn_gelu_kernel<<<(ROWS * DH / 4) / 256, 256>>>(out);
}

// round 16
// speedup vs baseline: 1.0561x; 1.0561x over previous
#include <cuda_runtime.h>
#include <cuda_fp16.h>
#include <math_constants.h>
#include <cstdint>

// Problem constants (fixed shapes)
#define BB 8
#define SS 2048
#define NN 8192
#define FF 256
#define CC 128
#define DIN 384
#define DH 512
#define ROWS (BB * NN)          // 65536
#define NBM (ROWS / 128)        // 512 row-tiles
#define EPSW 1.1920928955078125e-7f
#define BN_EPS 1e-5f

// -------- scratch (device globals; no allocation allowed) --------
__device__ __half g_x0h[(size_t)ROWS * DIN];    // fp16 concat(point_features, interp)
__device__ __half g_y1h[(size_t)ROWS * DH];     // fp16 GEMM1 out, then BN+GELU in-place
__device__ __half g_w1t[(size_t)DH * DIN];      // W1 transposed [n][k] fp16
__device__ __half g_w2t[(size_t)DH * DH];       // W2 transposed [n][k] fp16
__device__ float  g_part[2 * DH * NBM];         // [stat][col][bm] deterministic partials
__device__ float  g_scale[DH];
__device__ float  g_shift[DH];

// ======================= PTX helpers (portable sm_80+ subset) =======================
__device__ __forceinline__ uint32_t smem_u32(const void* p) {
    uint32_t a;
    asm("{ .reg .u64 t; cvta.to.shared.u64 t, %1; cvt.u32.u64 %0, t; }" : "=r"(a) : "l"(p));
    return a;
}
__device__ __forceinline__ void cp_async16(uint32_t dst, const void* src) {
    asm volatile("cp.async.cg.shared.global [%0], [%1], 16;" :: "r"(dst), "l"(src));
}
__device__ __forceinline__ void ldsm_x4(uint32_t* r, uint32_t addr) {
    asm volatile("ldmatrix.sync.aligned.m8n8.x4.shared.b16 {%0,%1,%2,%3}, [%4];"
                 : "=r"(r[0]), "=r"(r[1]), "=r"(r[2]), "=r"(r[3]) : "r"(addr));
}
__device__ __forceinline__ void mma16816(float* d, const uint32_t* a, const uint32_t* b) {
    asm volatile("mma.sync.aligned.m16n8k16.row.col.f32.f16.f16.f32 "
                 "{%0,%1,%2,%3}, {%4,%5,%6,%7}, {%8,%9}, {%0,%1,%2,%3};"
                 : "+f"(d[0]), "+f"(d[1]), "+f"(d[2]), "+f"(d[3])
                 : "r"(a[0]), "r"(a[1]), "r"(a[2]), "r"(a[3]), "r"(b[0]), "r"(b[1]));
}

// ======================= 1. 3-NN + interpolation (writes fp16) =======================
__global__ void interp_kernel(const float* __restrict__ sxyz,
                              const float* __restrict__ spf,
                              const float* __restrict__ xyz,
                              const float* __restrict__ pf) {
    __shared__ float sx[SS], sy[SS], sz[SS], sn[SS];
    __shared__ int   sidx[128][3];
    __shared__ float sw[128][3];

    const int b     = blockIdx.x >> 6;
    const int chunk = blockIdx.x & 63;
    const int t     = threadIdx.x;

    const float* sb = sxyz + (size_t)b * SS * 3;
    for (int s = t; s < SS; s += 128) {
        float x = sb[s * 3 + 0], y = sb[s * 3 + 1], z = sb[s * 3 + 2];
        sx[s] = x; sy[s] = y; sz[s] = z;
        sn[s] = x * x + y * y + z * z;
    }
    __syncthreads();

    const int p = chunk * 128 + t;
    const size_t prow = (size_t)b * NN + p;
    const float px = xyz[prow * 3 + 0];
    const float py = xyz[prow * 3 + 1];
    const float pz = xyz[prow * 3 + 2];
    const float n1 = px * px + py * py + pz * pz;

    float d0 = CUDART_INF_F, d1 = CUDART_INF_F, d2 = CUDART_INF_F;
    int   i0 = 0, i1 = 0, i2 = 0;
    for (int s = 0; s < SS; s++) {
        float dot = px * sx[s] + py * sy[s] + pz * sz[s];
        float d = __fadd_rn(__fadd_rn(__fmul_rn(-2.0f, dot), n1), sn[s]);
        if (d < d0)      { d2 = d1; i2 = i1; d1 = d0; i1 = i0; d0 = d; i0 = s; }
        else if (d < d1) { d2 = d1; i2 = i1; d1 = d;  i1 = s; }
        else if (d < d2) { d2 = d;  i2 = s; }
    }
    float w0 = 1.0f / (fmaxf(d0, 0.0f) + EPSW);
    float w1 = 1.0f / (fmaxf(d1, 0.0f) + EPSW);
    float w2 = 1.0f / (fmaxf(d2, 0.0f) + EPSW);
    float wsum = (w0 + w1) + w2;
    sidx[t][0] = i0; sidx[t][1] = i1; sidx[t][2] = i2;
    sw[t][0] = w0 / wsum; sw[t][1] = w1 / wsum; sw[t][2] = w2 / wsum;
    __syncthreads();

    const float* fb = spf + (size_t)b * SS * FF;
    const size_t rowbase = (size_t)b * NN + (size_t)chunk * 128;

    // gather: 2 points per iteration, float4 loads, uint2 (4xfp16) stores
    const int half_id = t >> 6;     // 0/1 -> which point of the pair
    const int tt = t & 63;          // float4 chunk within the 256-wide feature row
    for (int pl2 = 0; pl2 < 64; pl2++) {
        const int pl = pl2 * 2 + half_id;
        const int   j0 = sidx[pl][0], j1 = sidx[pl][1], j2 = sidx[pl][2];
        const float a0 = sw[pl][0],   a1 = sw[pl][1],   a2 = sw[pl][2];
        const float4* r0 = (const float4*)(fb + (size_t)j0 * FF);
        const float4* r1 = (const float4*)(fb + (size_t)j1 * FF);
        const float4* r2 = (const float4*)(fb + (size_t)j2 * FF);
        float4 v0 = r0[tt], v1 = r1[tt], v2 = r2[tt];
        float ax = (a0 * v0.x + a1 * v1.x) + a2 * v2.x;
        float ay = (a0 * v0.y + a1 * v1.y) + a2 * v2.y;
        float az = (a0 * v0.z + a1 * v1.z) + a2 * v2.z;
        float aw = (a0 * v0.w + a1 * v1.w) + a2 * v2.w;
        __half2 p0 = __floats2half2_rn(ax, ay);
        __half2 p1 = __floats2half2_rn(az, aw);
        uint2 u;
        u.x = *reinterpret_cast<uint32_t*>(&p0);
        u.y = *reinterpret_cast<uint32_t*>(&p1);
        *reinterpret_cast<uint2*>(g_x0h + (rowbase + pl) * DIN + CC + tt * 4) = u;
    }
    // copy point_features (128 cols) via float4 -> 4xfp16
    for (int idx = t; idx < 128 * CC / 4; idx += 128) {
        int pl = idx >> 5;          // 32 float4 per row
        int f4 = idx & 31;
        float4 v = ((const float4*)(pf + (rowbase + pl) * CC))[f4];
        __half2 p0 = __floats2half2_rn(v.x, v.y);
        __half2 p1 = __floats2half2_rn(v.z, v.w);
        uint2 u;
        u.x = *reinterpret_cast<uint32_t*>(&p0);
        u.y = *reinterpret_cast<uint32_t*>(&p1);
        *reinterpret_cast<uint2*>(g_x0h + (rowbase + pl) * DIN + f4 * 4) = u;
    }
}

// ======================= 2. weight prep: transpose to [n][k] fp16 =======================
__global__ void wprep_kernel(const float* __restrict__ W, __half* __restrict__ Wt, int K) {
    int i = blockIdx.x * blockDim.x + threadIdx.x;
    if (i >= K * DH) return;
    int k = i / DH, n = i % DH;
    Wt[(size_t)n * K + k] = __float2half(W[i]);
}

// ======================= 3. fp16 HGEMM (mma.sync m16n8k16) + fused BN stats =======================
// C tile 128x128, 4 warps (2x2), warp tile 64x64, BK=64, 3-stage cp.async pipeline.
// SINGLE __syncthreads per K-chunk: wait_group -> barrier -> issue load(c+2) -> compute(c).
// Buffer (c+2)%3 was last read at iter c-1; every warp past the barrier has finished it.
// Epilogue: stores C (fp16 or fp32) AND deterministic per-(col,bm) sum/sumsq partials.
#define HG_STAGE_BYTES 32768                 // A 16KB + B 16KB per stage
#define HG_SMEM (3 * HG_STAGE_BYTES)         // 96KB

template <int HALF_OUT>
__global__ __launch_bounds__(128, 2) void hgemm_kernel(
    const __half* __restrict__ A, const __half* __restrict__ Bt,
    void* __restrict__ Cv, int K) {
    extern __shared__ char smem[];
    const uint32_t sbase = smem_u32(smem);
    const int tid = threadIdx.x, wid = tid >> 5, lane = tid & 31;
    const int bn = blockIdx.x, bm = blockIdx.y;
    const int wm = wid >> 1, wn = wid & 1;     // 2 x 2 warp grid, tile 64x64

    const int lr = tid >> 3, lj = tid & 7;     // 16 rows x 8 chunks per pass, 8 passes
    const __half* ag = A + (size_t)(bm * 128) * K + lj * 8;
    const __half* bg = Bt + (size_t)(bn * 128) * K + lj * 8;

    float acc[4][8][4];
#pragma unroll
    for (int i = 0; i < 4; i++)
#pragma unroll
        for (int j = 0; j < 8; j++)
#pragma unroll
            for (int q = 0; q < 4; q++) acc[i][j][q] = 0.0f;

    auto load = [&](int c, int st) {
        uint32_t dA = sbase + st * HG_STAGE_BYTES;
        uint32_t dB = dA + 16384;
        const __half* a = ag + c * 64;
        const __half* b = bg + c * 64;
#pragma unroll
        for (int i = 0; i < 8; i++) {
            int r = lr + 16 * i;
            uint32_t so = (uint32_t)(r * 128 + lj * 16) ^ (uint32_t)((r & 7) << 4);
            cp_async16(dA + so, a + (size_t)r * K);
            cp_async16(dB + so, b + (size_t)r * K);
        }
        asm volatile("cp.async.commit_group;" ::: "memory");
    };

    const int CHN = K >> 6;
    load(0, 0);
    load(1, 1);
    for (int c = 0; c < CHN; c++) {
        const int st = c - (c / 3) * 3;   // c % 3
        if (c + 1 < CHN) {
            asm volatile("cp.async.wait_group 1;" ::: "memory");
        } else {
            asm volatile("cp.async.wait_group 0;" ::: "memory");
        }
        __syncthreads();
        if (c + 2 < CHN) {
            // safe: buffer (c+2)%3 == (c-1)%3 was consumed at iter c-1, and all
            // warps passed the barrier above only after finishing that compute.
            load(c + 2, (c + 2) - ((c + 2) / 3) * 3);
        }

        const uint32_t sA = sbase + st * HG_STAGE_BYTES;
        const uint32_t sB = sA + 16384;
#pragma unroll
        for (int s = 0; s < 4; s++) {
            uint32_t af[4][4];
            uint32_t bf[8][2];
#pragma unroll
            for (int i = 0; i < 4; i++) {
                int row = wm * 64 + i * 16 + (lane & 15);
                uint32_t off = (uint32_t)(row * 128 + s * 32 + (lane >> 4) * 16)
                             ^ (uint32_t)((row & 7) << 4);
                ldsm_x4(af[i], sA + off);
            }
#pragma unroll
            for (int u = 0; u < 4; u++) {
                int n  = wn * 64 + u * 16 + ((lane >> 4) * 8) + (lane & 7);
                int kh = (lane >> 3) & 1;
                uint32_t off = (uint32_t)(n * 128 + s * 32 + kh * 16)
                             ^ (uint32_t)((n & 7) << 4);
                uint32_t r4[4];
                ldsm_x4(r4, sB + off);
                bf[2 * u][0] = r4[0]; bf[2 * u][1] = r4[1];
                bf[2 * u + 1][0] = r4[2]; bf[2 * u + 1][1] = r4[3];
            }
#pragma unroll
            for (int i = 0; i < 4; i++)
#pragma unroll
                for (int j = 0; j < 8; j++)
                    mma16816(acc[i][j], af[i], bf[j]);
        }
        // no trailing barrier: next iteration's barrier protects buffer reuse
    }

    // ---- epilogue: store C ----
    const int r = lane >> 2, cc = (lane & 3) * 2;
    if (HALF_OUT) {
        __half* Cp = (__half*)Cv + (size_t)(bm * 128 + wm * 64) * DH + bn * 128 + wn * 64;
#pragma unroll
        for (int i = 0; i < 4; i++) {
#pragma unroll
            for (int j = 0; j < 8; j++) {
                __half2 v0 = __floats2half2_rn(acc[i][j][0], acc[i][j][1]);
                __half2 v1 = __floats2half2_rn(acc[i][j][2], acc[i][j][3]);
                *(__half2*)(Cp + (size_t)(i * 16 + r) * DH + j * 8 + cc) = v0;
                *(__half2*)(Cp + (size_t)(i * 16 + r + 8) * DH + j * 8 + cc) = v1;
            }
        }
    } else {
        float* Cp = (float*)Cv + (size_t)(bm * 128 + wm * 64) * DH + bn * 128 + wn * 64;
#pragma unroll
        for (int i = 0; i < 4; i++) {
#pragma unroll
            for (int j = 0; j < 8; j++) {
                float2 v0 = make_float2(acc[i][j][0], acc[i][j][1]);
                float2 v1 = make_float2(acc[i][j][2], acc[i][j][3]);
                *(float2*)(Cp + (size_t)(i * 16 + r) * DH + j * 8 + cc) = v0;
                *(float2*)(Cp + (size_t)(i * 16 + r + 8) * DH + j * 8 + cc) = v1;
            }
        }
    }

    // ---- epilogue: deterministic per-(col, bm) BN partials from fp32 accumulators ----
    // per-thread: 16 column slots (j in 0..7, qp in 0..1); sum over i and row halves
    float sS[16], sQ[16];
#pragma unroll
    for (int j = 0; j < 8; j++) {
#pragma unroll
        for (int qp = 0; qp < 2; qp++) {
            float s = 0.f, q = 0.f;
#pragma unroll
            for (int i = 0; i < 4; i++) {
                float a = acc[i][j][qp];
                float b = acc[i][j][2 + qp];
                s += a + b;
                q += a * a + b * b;
            }
            sS[j * 2 + qp] = s;
            sQ[j * 2 + qp] = q;
        }
    }
    // reduce over the 8 row-lanes (lanes sharing lane&3): xor tree, fixed order
#pragma unroll
    for (int off = 4; off <= 16; off <<= 1) {
#pragma unroll
        for (int sl = 0; sl < 16; sl++) {
            sS[sl] += __shfl_xor_sync(0xFFFFFFFFu, sS[sl], off);
            sQ[sl] += __shfl_xor_sync(0xFFFFFFFFu, sQ[sl], off);
        }
    }
    // stage per-warp 64-col results in smem: [wm][stat][128 cols]
    float* sbuf = (float*)smem;
    __syncthreads();   // all cp.async/ldsm done; orders smem reuse
    if (lane < 4) {
#pragma unroll
        for (int j = 0; j < 8; j++) {
#pragma unroll
            for (int qp = 0; qp < 2; qp++) {
                int col = wn * 64 + j * 8 + lane * 2 + qp;
                sbuf[(wm * 2 + 0) * 128 + col] = sS[j * 2 + qp];
                sbuf[(wm * 2 + 1) * 128 + col] = sQ[j * 2 + qp];
            }
        }
    }
    __syncthreads();
    if (tid < 128) {
        float S = sbuf[0 * 128 + tid] + sbuf[2 * 128 + tid];
        float Q = sbuf[1 * 128 + tid] + sbuf[3 * 128 + tid];
        int colg = bn * 128 + tid;
        g_part[0 * DH * NBM + (size_t)colg * NBM + bm] = S;
        g_part[1 * DH * NBM + (size_t)colg * NBM + bm] = Q;
    }
}

// ======================= 4. finalize BN: reduce 512 partials per column =======================
__global__ void finalize_bn_kernel(const float* __restrict__ gamma,
                                   const float* __restrict__ beta) {
    const int c = blockIdx.x;
    const int t = threadIdx.x;   // 256
    float s = g_part[(size_t)c * NBM + t] + g_part[(size_t)c * NBM + t + 256];
    float q = g_part[DH * NBM + (size_t)c * NBM + t] +
              g_part[DH * NBM + (size_t)c * NBM + t + 256];
#pragma unroll
    for (int o = 16; o > 0; o >>= 1) {
        s += __shfl_down_sync(0xFFFFFFFFu, s, o);
        q += __shfl_down_sync(0xFFFFFFFFu, q, o);
    }
    __shared__ float ss[8], qq[8];
    if ((t & 31) == 0) { ss[t >> 5] = s; qq[t >> 5] = q; }
    __syncthreads();
    if (t == 0) {
        float S = 0.f, Q = 0.f;
#pragma unroll
        for (int i = 0; i < 8; i++) { S += ss[i]; Q += qq[i]; }
        const float inv = 1.0f / (float)ROWS;
        float mean = S * inv;
        float var  = Q * inv - mean * mean;
        float sc = gamma[c] * rsqrtf(var + BN_EPS);
        g_scale[c] = sc;
        g_shift[c] = beta[c] - mean * sc;
    }
}

// ======================= 5. fused BN + exact GELU =======================
__device__ __forceinline__ float gelu_exact(float x) {
    return 0.5f * x * (1.0f + erff(x * 0.70710678118654752f));
}

// layer-1: in-place on fp16 y1h (4 halves per thread)
__global__ void bn_gelu_h_kernel(__half* __restrict__ H) {
    const int i = blockIdx.x * blockDim.x + threadIdx.x;   // 4-half chunk index
    uint2 u = ((const uint2*)H)[i];
    __half2 p0 = *reinterpret_cast<__half2*>(&u.x);
    __half2 p1 = *reinterpret_cast<__half2*>(&u.y);
    const int col = (i * 4) & (DH - 1);
    float t0 = gelu_exact(__half2float(p0.x) * g_scale[col + 0] + g_shift[col + 0]);
    float t1 = gelu_exact(__half2float(p0.y) * g_scale[col + 1] + g_shift[col + 1]);
    float t2 = gelu_exact(__half2float(p1.x) * g_scale[col + 2] + g_shift[col + 2]);
    float t3 = gelu_exact(__half2float(p1.y) * g_scale[col + 3] + g_shift[col + 3]);
    __half2 q0 = __floats2half2_rn(t0, t1);
    __half2 q1 = __floats2half2_rn(t2, t3);
    u.x = *reinterpret_cast<uint32_t*>(&q0);
    u.y = *reinterpret_cast<uint32_t*>(&q1);
    ((uint2*)H)[i] = u;
}

// final layer: in-place fp32
__global__ void bn_gelu_kernel(float* __restrict__ Y) {
    const int i = blockIdx.x * blockDim.x + threadIdx.x;
    float4 v = ((float4*)Y)[i];
    const int col = (i * 4) & (DH - 1);
    v.x = gelu_exact(v.x * g_scale[col + 0] + g_shift[col + 0]);
    v.y = gelu_exact(v.y * g_scale[col + 1] + g_shift[col + 1]);
    v.z = gelu_exact(v.z * g_scale[col + 2] + g_shift[col + 2]);
    v.w = gelu_exact(v.w * g_scale[col + 3] + g_shift[col + 3]);
    ((float4*)Y)[i] = v;
}

// ======================= host launch =======================
extern "C" void kernel_launch(void* const* d_in, const int* in_sizes, int n_in,
                              void* d_out, int out_size) {
    const float* sxyz = (const float*)d_in[0];
    const float* spf  = (const float*)d_in[1];
    const float* xyz  = (const float*)d_in[2];
    const float* pf   = (const float*)d_in[3];
    const float* W1   = (const float*)d_in[4];
    const float* g1   = (const float*)d_in[5];
    const float* b1   = (const float*)d_in[6];
    const float* W2   = (const float*)d_in[7];
    const float* g2   = (const float*)d_in[8];
    const float* b2   = (const float*)d_in[9];
    float* out = (float*)d_out;

    void *p_x0h, *p_y1h, *p_w1t, *p_w2t;
    cudaGetSymbolAddress(&p_x0h, g_x0h);
    cudaGetSymbolAddress(&p_y1h, g_y1h);
    cudaGetSymbolAddress(&p_w1t, g_w1t);
    cudaGetSymbolAddress(&p_w2t, g_w2t);

    cudaFuncSetAttribute(hgemm_kernel<1>, cudaFuncAttributeMaxDynamicSharedMemorySize, HG_SMEM);
    cudaFuncSetAttribute(hgemm_kernel<0>, cudaFuncAttributeMaxDynamicSharedMemorySize, HG_SMEM);

    // 1. 3-NN interpolation + concat -> x0 fp16 [65536, 384]
    interp_kernel<<<BB * 64, 128>>>(sxyz, spf, xyz, pf);

    // 2. weight transpose to fp16 (tiny)
    wprep_kernel<<<(DIN * DH + 255) / 256, 256>>>(W1, (__half*)p_w1t, DIN);
    wprep_kernel<<<(DH * DH + 255) / 256, 256>>>(W2, (__half*)p_w2t, DH);

    // 3. y1h = x0 @ W1 (fp16 out) + fused BN partials
    {
        dim3 grid(DH / 128, ROWS / 128);
        hgemm_kernel<1><<<grid, 128, HG_SMEM>>>((const __half*)p_x0h, (const __half*)p_w1t,
                                                p_y1h, DIN);
    }

    // 4. finalize BN-1, then fused BN+GELU in-place on y1h (fp16)
    finalize_bn_kernel<<<DH, 256>>>(g1, b1);
    bn_gelu_h_kernel<<<(ROWS * DH / 4) / 256, 256>>>((__half*)p_y1h);

    // 5. out = y1h @ W2 (fp32 out) + fused BN partials
    {
        dim3 grid(DH / 128, ROWS / 128);
        hgemm_kernel<0><<<grid, 128, HG_SMEM>>>((const __half*)p_y1h, (const __half*)p_w2t,
                                                out, DH);
    }

    // 6. finalize BN-2 + fused BN+GELU in-place on out (fp32)
    finalize_bn_kernel<<<DH, 256>>>(g2, b2);
    bn_gelu_kernel<<<(ROWS * DH / 4) / 256, 256>>>(out);
}

// round 17
// speedup vs baseline: 1.1483x; 1.0874x over previous
#include <cuda_runtime.h>
#include <cuda_fp16.h>
#include <math_constants.h>
#include <cstdint>

// Problem constants (fixed shapes)
#define BB 8
#define SS 2048
#define NN 8192
#define FF 256
#define CC 128
#define DIN 384
#define DH 512
#define ROWS (BB * NN)          // 65536
#define NBM (ROWS / 128)        // 512 row-tiles
#define EPSW 1.1920928955078125e-7f
#define BN_EPS 1e-5f

// -------- scratch (device globals; no allocation allowed) --------
__device__ __half g_x0h[(size_t)ROWS * DIN];    // fp16 concat(point_features, interp)
__device__ __half g_y1h[(size_t)ROWS * DH];     // fp16 GEMM1 out, then BN+GELU in-place
__device__ __half g_w1t[(size_t)DH * DIN];      // W1 transposed [n][k] fp16
__device__ __half g_w2t[(size_t)DH * DH];       // W2 transposed [n][k] fp16
__device__ float  g_part[2 * DH * NBM];         // [stat][col][bm] deterministic partials
__device__ float  g_scale[DH];
__device__ float  g_shift[DH];

// ======================= PTX helpers (portable sm_80+ subset) =======================
__device__ __forceinline__ uint32_t smem_u32(const void* p) {
    uint32_t a;
    asm("{ .reg .u64 t; cvta.to.shared.u64 t, %1; cvt.u32.u64 %0, t; }" : "=r"(a) : "l"(p));
    return a;
}
__device__ __forceinline__ void cp_async16(uint32_t dst, const void* src) {
    asm volatile("cp.async.cg.shared.global [%0], [%1], 16;" :: "r"(dst), "l"(src));
}
__device__ __forceinline__ void ldsm_x4(uint32_t* r, uint32_t addr) {
    asm volatile("ldmatrix.sync.aligned.m8n8.x4.shared.b16 {%0,%1,%2,%3}, [%4];"
                 : "=r"(r[0]), "=r"(r[1]), "=r"(r[2]), "=r"(r[3]) : "r"(addr));
}
__device__ __forceinline__ void mma16816(float* d, const uint32_t* a, const uint32_t* b) {
    asm volatile("mma.sync.aligned.m16n8k16.row.col.f32.f16.f16.f32 "
                 "{%0,%1,%2,%3}, {%4,%5,%6,%7}, {%8,%9}, {%0,%1,%2,%3};"
                 : "+f"(d[0]), "+f"(d[1]), "+f"(d[2]), "+f"(d[3])
                 : "r"(a[0]), "r"(a[1]), "r"(a[2]), "r"(a[3]), "r"(b[0]), "r"(b[1]));
}

// ======================= 1. 3-NN + interpolation (writes fp16) =======================
// KNN via e = dot - 0.5*|s|^2 (descending) == d = -2*dot + |p|^2 + |s|^2 (ascending),
// computed as one 3-FMA chain per superpoint. d reconstructed as max(n1 - 2e, 0).
__global__ void interp_kernel(const float* __restrict__ sxyz,
                              const float* __restrict__ spf,
                              const float* __restrict__ xyz,
                              const float* __restrict__ pf) {
    __shared__ float sx[SS], sy[SS], sz[SS], snh[SS];
    __shared__ int   sidx[128][3];
    __shared__ float sw[128][3];

    const int b     = blockIdx.x >> 6;
    const int chunk = blockIdx.x & 63;
    const int t     = threadIdx.x;

    const float* sb = sxyz + (size_t)b * SS * 3;
    for (int s = t; s < SS; s += 128) {
        float x = sb[s * 3 + 0], y = sb[s * 3 + 1], z = sb[s * 3 + 2];
        sx[s] = x; sy[s] = y; sz[s] = z;
        snh[s] = 0.5f * (x * x + y * y + z * z);
    }
    __syncthreads();

    const int p = chunk * 128 + t;
    const size_t prow = (size_t)b * NN + p;
    const float px = xyz[prow * 3 + 0];
    const float py = xyz[prow * 3 + 1];
    const float pz = xyz[prow * 3 + 2];
    const float n1 = px * px + py * py + pz * pz;

    float e0 = -CUDART_INF_F, e1 = -CUDART_INF_F, e2 = -CUDART_INF_F;
    int   i0 = 0, i1 = 0, i2 = 0;
    for (int s = 0; s < SS; s++) {
        float e = fmaf(pz, sz[s], fmaf(py, sy[s], fmaf(px, sx[s], -snh[s])));
        if (e > e2) {                      // rare after warmup
            if (e > e0)      { e2 = e1; i2 = i1; e1 = e0; i1 = i0; e0 = e; i0 = s; }
            else if (e > e1) { e2 = e1; i2 = i1; e1 = e;  i1 = s; }
            else             { e2 = e;  i2 = s; }
        }
    }
    float d0 = fmaxf(fmaf(-2.0f, e0, n1), 0.0f);
    float d1 = fmaxf(fmaf(-2.0f, e1, n1), 0.0f);
    float d2 = fmaxf(fmaf(-2.0f, e2, n1), 0.0f);
    float w0 = 1.0f / (d0 + EPSW);
    float w1 = 1.0f / (d1 + EPSW);
    float w2 = 1.0f / (d2 + EPSW);
    float wsum = (w0 + w1) + w2;
    sidx[t][0] = i0; sidx[t][1] = i1; sidx[t][2] = i2;
    sw[t][0] = w0 / wsum; sw[t][1] = w1 / wsum; sw[t][2] = w2 / wsum;
    __syncthreads();

    const float* fb = spf + (size_t)b * SS * FF;
    const size_t rowbase = (size_t)b * NN + (size_t)chunk * 128;

    // gather: 2 points per iteration, float4 loads, uint2 (4xfp16) stores
    const int half_id = t >> 6;     // 0/1 -> which point of the pair
    const int tt = t & 63;          // float4 chunk within the 256-wide feature row
    for (int pl2 = 0; pl2 < 64; pl2++) {
        const int pl = pl2 * 2 + half_id;
        const int   j0 = sidx[pl][0], j1 = sidx[pl][1], j2 = sidx[pl][2];
        const float a0 = sw[pl][0],   a1 = sw[pl][1],   a2 = sw[pl][2];
        const float4* r0 = (const float4*)(fb + (size_t)j0 * FF);
        const float4* r1 = (const float4*)(fb + (size_t)j1 * FF);
        const float4* r2 = (const float4*)(fb + (size_t)j2 * FF);
        float4 v0 = r0[tt], v1 = r1[tt], v2 = r2[tt];
        float ax = (a0 * v0.x + a1 * v1.x) + a2 * v2.x;
        float ay = (a0 * v0.y + a1 * v1.y) + a2 * v2.y;
        float az = (a0 * v0.z + a1 * v1.z) + a2 * v2.z;
        float aw = (a0 * v0.w + a1 * v1.w) + a2 * v2.w;
        __half2 p0 = __floats2half2_rn(ax, ay);
        __half2 p1 = __floats2half2_rn(az, aw);
        uint2 u;
        u.x = *reinterpret_cast<uint32_t*>(&p0);
        u.y = *reinterpret_cast<uint32_t*>(&p1);
        *reinterpret_cast<uint2*>(g_x0h + (rowbase + pl) * DIN + CC + tt * 4) = u;
    }
    // copy point_features (128 cols) via float4 -> 4xfp16
    for (int idx = t; idx < 128 * CC / 4; idx += 128) {
        int pl = idx >> 5;          // 32 float4 per row
        int f4 = idx & 31;
        float4 v = ((const float4*)(pf + (rowbase + pl) * CC))[f4];
        __half2 p0 = __floats2half2_rn(v.x, v.y);
        __half2 p1 = __floats2half2_rn(v.z, v.w);
        uint2 u;
        u.x = *reinterpret_cast<uint32_t*>(&p0);
        u.y = *reinterpret_cast<uint32_t*>(&p1);
        *reinterpret_cast<uint2*>(g_x0h + (rowbase + pl) * DIN + f4 * 4) = u;
    }
}

// ======================= 2. weight prep: both weights in ONE launch =======================
// W [K][512] fp32 -> Wt [512][K] fp16 (rows = output col n, K-major)
__global__ void wprep_kernel(const float* __restrict__ W1, __half* __restrict__ W1t,
                             const float* __restrict__ W2, __half* __restrict__ W2t) {
    int i = blockIdx.x * blockDim.x + threadIdx.x;
    if (i < DIN * DH) {
        int k = i / DH, n = i % DH;
        W1t[(size_t)n * DIN + k] = __float2half(W1[i]);
    }
    int j = i - DIN * DH;
    if (j >= 0 && j < DH * DH) {
        int k = j / DH, n = j % DH;
        W2t[(size_t)n * DH + k] = __float2half(W2[j]);
    }
}

// ======================= 3. fp16 HGEMM (mma.sync m16n8k16) + fused BN stats =======================
// C tile 128x128, 4 warps (2x2), warp tile 64x64, BK=64, 3-stage cp.async pipeline.
// SINGLE __syncthreads per K-chunk: wait_group -> barrier -> issue load(c+2) -> compute(c).
#define HG_STAGE_BYTES 32768                 // A 16KB + B 16KB per stage
#define HG_SMEM (3 * HG_STAGE_BYTES)         // 96KB

template <int HALF_OUT>
__global__ __launch_bounds__(128, 2) void hgemm_kernel(
    const __half* __restrict__ A, const __half* __restrict__ Bt,
    void* __restrict__ Cv, int K) {
    extern __shared__ char smem[];
    const uint32_t sbase = smem_u32(smem);
    const int tid = threadIdx.x, wid = tid >> 5, lane = tid & 31;
    const int bn = blockIdx.x, bm = blockIdx.y;
    const int wm = wid >> 1, wn = wid & 1;     // 2 x 2 warp grid, tile 64x64

    const int lr = tid >> 3, lj = tid & 7;     // 16 rows x 8 chunks per pass, 8 passes
    const __half* ag = A + (size_t)(bm * 128) * K + lj * 8;
    const __half* bg = Bt + (size_t)(bn * 128) * K + lj * 8;

    float acc[4][8][4];
#pragma unroll
    for (int i = 0; i < 4; i++)
#pragma unroll
        for (int j = 0; j < 8; j++)
#pragma unroll
            for (int q = 0; q < 4; q++) acc[i][j][q] = 0.0f;

    auto load = [&](int c, int st) {
        uint32_t dA = sbase + st * HG_STAGE_BYTES;
        uint32_t dB = dA + 16384;
        const __half* a = ag + c * 64;
        const __half* b = bg + c * 64;
#pragma unroll
        for (int i = 0; i < 8; i++) {
            int r = lr + 16 * i;
            uint32_t so = (uint32_t)(r * 128 + lj * 16) ^ (uint32_t)((r & 7) << 4);
            cp_async16(dA + so, a + (size_t)r * K);
            cp_async16(dB + so, b + (size_t)r * K);
        }
        asm volatile("cp.async.commit_group;" ::: "memory");
    };

    const int CHN = K >> 6;
    load(0, 0);
    load(1, 1);
    for (int c = 0; c < CHN; c++) {
        const int st = c - (c / 3) * 3;   // c % 3
        if (c + 1 < CHN) {
            asm volatile("cp.async.wait_group 1;" ::: "memory");
        } else {
            asm volatile("cp.async.wait_group 0;" ::: "memory");
        }
        __syncthreads();
        if (c + 2 < CHN) {
            // safe: buffer (c+2)%3 == (c-1)%3 was consumed at iter c-1, and all
            // warps passed the barrier above only after finishing that compute.
            load(c + 2, (c + 2) - ((c + 2) / 3) * 3);
        }

        const uint32_t sA = sbase + st * HG_STAGE_BYTES;
        const uint32_t sB = sA + 16384;
#pragma unroll
        for (int s = 0; s < 4; s++) {
            uint32_t af[4][4];
            uint32_t bf[8][2];
#pragma unroll
            for (int i = 0; i < 4; i++) {
                int row = wm * 64 + i * 16 + (lane & 15);
                uint32_t off = (uint32_t)(row * 128 + s * 32 + (lane >> 4) * 16)
                             ^ (uint32_t)((row & 7) << 4);
                ldsm_x4(af[i], sA + off);
            }
#pragma unroll
            for (int u = 0; u < 4; u++) {
                int n  = wn * 64 + u * 16 + ((lane >> 4) * 8) + (lane & 7);
                int kh = (lane >> 3) & 1;
                uint32_t off = (uint32_t)(n * 128 + s * 32 + kh * 16)
                             ^ (uint32_t)((n & 7) << 4);
                uint32_t r4[4];
                ldsm_x4(r4, sB + off);
                bf[2 * u][0] = r4[0]; bf[2 * u][1] = r4[1];
                bf[2 * u + 1][0] = r4[2]; bf[2 * u + 1][1] = r4[3];
            }
#pragma unroll
            for (int i = 0; i < 4; i++)
#pragma unroll
                for (int j = 0; j < 8; j++)
                    mma16816(acc[i][j], af[i], bf[j]);
        }
        // no trailing barrier: next iteration's barrier protects buffer reuse
    }

    // ---- epilogue: store C ----
    const int r = lane >> 2, cc = (lane & 3) * 2;
    if (HALF_OUT) {
        __half* Cp = (__half*)Cv + (size_t)(bm * 128 + wm * 64) * DH + bn * 128 + wn * 64;
#pragma unroll
        for (int i = 0; i < 4; i++) {
#pragma unroll
            for (int j = 0; j < 8; j++) {
                __half2 v0 = __floats2half2_rn(acc[i][j][0], acc[i][j][1]);
                __half2 v1 = __floats2half2_rn(acc[i][j][2], acc[i][j][3]);
                *(__half2*)(Cp + (size_t)(i * 16 + r) * DH + j * 8 + cc) = v0;
                *(__half2*)(Cp + (size_t)(i * 16 + r + 8) * DH + j * 8 + cc) = v1;
            }
        }
    } else {
        float* Cp = (float*)Cv + (size_t)(bm * 128 + wm * 64) * DH + bn * 128 + wn * 64;
#pragma unroll
        for (int i = 0; i < 4; i++) {
#pragma unroll
            for (int j = 0; j < 8; j++) {
                float2 v0 = make_float2(acc[i][j][0], acc[i][j][1]);
                float2 v1 = make_float2(acc[i][j][2], acc[i][j][3]);
                *(float2*)(Cp + (size_t)(i * 16 + r) * DH + j * 8 + cc) = v0;
                *(float2*)(Cp + (size_t)(i * 16 + r + 8) * DH + j * 8 + cc) = v1;
            }
        }
    }

    // ---- epilogue: deterministic per-(col, bm) BN partials from fp32 accumulators ----
    float sS[16], sQ[16];
#pragma unroll
    for (int j = 0; j < 8; j++) {
#pragma unroll
        for (int qp = 0; qp < 2; qp++) {
            float s = 0.f, q = 0.f;
#pragma unroll
            for (int i = 0; i < 4; i++) {
                float a = acc[i][j][qp];
                float b = acc[i][j][2 + qp];
                s += a + b;
                q += a * a + b * b;
            }
            sS[j * 2 + qp] = s;
            sQ[j * 2 + qp] = q;
        }
    }
    // reduce over the 8 row-lanes (lanes sharing lane&3): xor tree, fixed order
#pragma unroll
    for (int off = 4; off <= 16; off <<= 1) {
#pragma unroll
        for (int sl = 0; sl < 16; sl++) {
            sS[sl] += __shfl_xor_sync(0xFFFFFFFFu, sS[sl], off);
            sQ[sl] += __shfl_xor_sync(0xFFFFFFFFu, sQ[sl], off);
        }
    }
    // stage per-warp 64-col results in smem: [wm][stat][128 cols]
    float* sbuf = (float*)smem;
    __syncthreads();   // all cp.async/ldsm done; orders smem reuse
    if (lane < 4) {
#pragma unroll
        for (int j = 0; j < 8; j++) {
#pragma unroll
            for (int qp = 0; qp < 2; qp++) {
                int col = wn * 64 + j * 8 + lane * 2 + qp;
                sbuf[(wm * 2 + 0) * 128 + col] = sS[j * 2 + qp];
                sbuf[(wm * 2 + 1) * 128 + col] = sQ[j * 2 + qp];
            }
        }
    }
    __syncthreads();
    if (tid < 128) {
        float S = sbuf[0 * 128 + tid] + sbuf[2 * 128 + tid];
        float Q = sbuf[1 * 128 + tid] + sbuf[3 * 128 + tid];
        int colg = bn * 128 + tid;
        g_part[0 * DH * NBM + (size_t)colg * NBM + bm] = S;
        g_part[1 * DH * NBM + (size_t)colg * NBM + bm] = Q;
    }
}

// ======================= 4. finalize BN: reduce 512 partials per column =======================
__global__ void finalize_bn_kernel(const float* __restrict__ gamma,
                                   const float* __restrict__ beta) {
    const int c = blockIdx.x;
    const int t = threadIdx.x;   // 256
    float s = g_part[(size_t)c * NBM + t] + g_part[(size_t)c * NBM + t + 256];
    float q = g_part[DH * NBM + (size_t)c * NBM + t] +
              g_part[DH * NBM + (size_t)c * NBM + t + 256];
#pragma unroll
    for (int o = 16; o > 0; o >>= 1) {
        s += __shfl_down_sync(0xFFFFFFFFu, s, o);
        q += __shfl_down_sync(0xFFFFFFFFu, q, o);
    }
    __shared__ float ss[8], qq[8];
    if ((t & 31) == 0) { ss[t >> 5] = s; qq[t >> 5] = q; }
    __syncthreads();
    if (t == 0) {
        float S = 0.f, Q = 0.f;
#pragma unroll
        for (int i = 0; i < 8; i++) { S += ss[i]; Q += qq[i]; }
        const float inv = 1.0f / (float)ROWS;
        float mean = S * inv;
        float var  = Q * inv - mean * mean;
        float sc = gamma[c] * rsqrtf(var + BN_EPS);
        g_scale[c] = sc;
        g_shift[c] = beta[c] - mean * sc;
    }
}

// ======================= 5. fused BN + exact GELU =======================
__device__ __forceinline__ float gelu_exact(float x) {
    return 0.5f * x * (1.0f + erff(x * 0.70710678118654752f));
}

// layer-1: in-place on fp16 y1h (4 halves per thread)
__global__ void bn_gelu_h_kernel(__half* __restrict__ H) {
    const int i = blockIdx.x * blockDim.x + threadIdx.x;   // 4-half chunk index
    uint2 u = ((const uint2*)H)[i];
    __half2 p0 = *reinterpret_cast<__half2*>(&u.x);
    __half2 p1 = *reinterpret_cast<__half2*>(&u.y);
    const int col = (i * 4) & (DH - 1);
    float t0 = gelu_exact(__half2float(p0.x) * g_scale[col + 0] + g_shift[col + 0]);
    float t1 = gelu_exact(__half2float(p0.y) * g_scale[col + 1] + g_shift[col + 1]);
    float t2 = gelu_exact(__half2float(p1.x) * g_scale[col + 2] + g_shift[col + 2]);
    float t3 = gelu_exact(__half2float(p1.y) * g_scale[col + 3] + g_shift[col + 3]);
    __half2 q0 = __floats2half2_rn(t0, t1);
    __half2 q1 = __floats2half2_rn(t2, t3);
    u.x = *reinterpret_cast<uint32_t*>(&q0);
    u.y = *reinterpret_cast<uint32_t*>(&q1);
    ((uint2*)H)[i] = u;
}

// final layer: in-place fp32
__global__ void bn_gelu_kernel(float* __restrict__ Y) {
    const int i = blockIdx.x * blockDim.x + threadIdx.x;
    float4 v = ((float4*)Y)[i];
    const int col = (i * 4) & (DH - 1);
    v.x = gelu_exact(v.x * g_scale[col + 0] + g_shift[col + 0]);
    v.y = gelu_exact(v.y * g_scale[col + 1] + g_shift[col + 1]);
    v.z = gelu_exact(v.z * g_scale[col + 2] + g_shift[col + 2]);
    v.w = gelu_exact(v.w * g_scale[col + 3] + g_shift[col + 3]);
    ((float4*)Y)[i] = v;
}

// ======================= host launch =======================
extern "C" void kernel_launch(void* const* d_in, const int* in_sizes, int n_in,
                              void* d_out, int out_size) {
    const float* sxyz = (const float*)d_in[0];
    const float* spf  = (const float*)d_in[1];
    const float* xyz  = (const float*)d_in[2];
    const float* pf   = (const float*)d_in[3];
    const float* W1   = (const float*)d_in[4];
    const float* g1   = (const float*)d_in[5];
    const float* b1   = (const float*)d_in[6];
    const float* W2   = (const float*)d_in[7];
    const float* g2   = (const float*)d_in[8];
    const float* b2   = (const float*)d_in[9];
    float* out = (float*)d_out;

    void *p_x0h, *p_y1h, *p_w1t, *p_w2t;
    cudaGetSymbolAddress(&p_x0h, g_x0h);
    cudaGetSymbolAddress(&p_y1h, g_y1h);
    cudaGetSymbolAddress(&p_w1t, g_w1t);
    cudaGetSymbolAddress(&p_w2t, g_w2t);

    cudaFuncSetAttribute(hgemm_kernel<1>, cudaFuncAttributeMaxDynamicSharedMemorySize, HG_SMEM);
    cudaFuncSetAttribute(hgemm_kernel<0>, cudaFuncAttributeMaxDynamicSharedMemorySize, HG_SMEM);

    // 1. 3-NN interpolation + concat -> x0 fp16 [65536, 384]
    interp_kernel<<<BB * 64, 128>>>(sxyz, spf, xyz, pf);

    // 2. both weight transposes in one launch
    wprep_kernel<<<((DIN + DH) * DH + 255) / 256, 256>>>(W1, (__half*)p_w1t,
                                                         W2, (__half*)p_w2t);

    // 3. y1h = x0 @ W1 (fp16 out) + fused BN partials
    {
        dim3 grid(DH / 128, ROWS / 128);
        hgemm_kernel<1><<<grid, 128, HG_SMEM>>>((const __half*)p_x0h, (const __half*)p_w1t,
                                                p_y1h, DIN);
    }

    // 4. finalize BN-1, then fused BN+GELU in-place on y1h (fp16)
    finalize_bn_kernel<<<DH, 256>>>(g1, b1);
    bn_gelu_h_kernel<<<(ROWS * DH / 4) / 256, 256>>>((__half*)p_y1h);

    // 5. out = y1h @ W2 (fp32 out) + fused BN partials
    {
        dim3 grid(DH / 128, ROWS / 128);
        hgemm_kernel<0><<<grid, 128, HG_SMEM>>>((const __half*)p_y1h, (const __half*)p_w2t,
                                                out, DH);
    }

    // 6. finalize BN-2 + fused BN+GELU in-place on out (fp32)
    finalize_bn_kernel<<<DH, 256>>>(g2, b2);
    bn_gelu_kernel<<<(ROWS * DH / 4) / 256, 256>>>(out);
}